// round 1
// baseline (speedup 1.0000x reference)
#include <cuda_runtime.h>
#include <math.h>

#define NC 512
#define NPIX 1024

// ---------------- scratch (no allocations allowed) ----------------
__device__ float g_y[NC];                 // channel means
__device__ float g_s[NC];                 // SE scales
__device__ float g_A[32 * 32];            // row-stochastic gaussian matrix A[i][x]
__device__ float g_f0t[NPIX * NC];        // f0 transposed: [pix][ch]
__device__ float g_sigt[NPIX * NC];       // sigmoid(f0): [pix][ch]
__device__ float g_cat[2 * NPIX * NC];    // [0..512K): gus flat (pix-major), [512K..1M): csa flat

// ---------------- 1. gaussian matrix init ----------------
__global__ void k_initA() {
    int i = threadIdx.x >> 5, x = threadIdx.x & 31;
    double d = (double)(x - i);
    double e = exp(-d * d / 4.5);   // 2*v^2 = 4.5 ; the 1/(2*pi*v^2) cancels in normalization
    double s = e;
    #pragma unroll
    for (int o = 16; o; o >>= 1) s += __shfl_down_sync(0xffffffffu, s, o);
    s = __shfl_sync(0xffffffffu, s, 0);
    g_A[i * 32 + x] = (float)(e / s);
}

// ---------------- 2. per-channel mean ----------------
__global__ void k_mean(const float* __restrict__ x) {
    int c = blockIdx.x, t = threadIdx.x;
    float4 v = ((const float4*)(x + c * 1024))[t];
    float s = v.x + v.y + v.z + v.w;
    #pragma unroll
    for (int o = 16; o; o >>= 1) s += __shfl_down_sync(0xffffffffu, s, o);
    __shared__ float ws[8];
    if ((t & 31) == 0) ws[t >> 5] = s;
    __syncthreads();
    if (t == 0) {
        float tot = 0.f;
        #pragma unroll
        for (int i = 0; i < 8; i++) tot += ws[i];
        g_y[c] = tot * (1.f / 1024.f);
    }
}

// ---------------- 3. SE MLP: 512 -> 32 (relu) -> 512 (sigmoid) ----------------
__global__ void k_mlp(const float* __restrict__ w1, const float* __restrict__ b1,
                      const float* __restrict__ w2, const float* __restrict__ b2) {
    __shared__ float sy[512];
    __shared__ float sh[32];
    int t = threadIdx.x;
    if (t < 512) sy[t] = g_y[t];
    __syncthreads();
    int r = t >> 5, lane = t & 31;   // 32 warps, one per hidden unit
    float a = 0.f;
    for (int c = lane; c < 512; c += 32) a += sy[c] * w1[r * 512 + c];
    #pragma unroll
    for (int o = 16; o; o >>= 1) a += __shfl_down_sync(0xffffffffu, a, o);
    if (lane == 0) sh[r] = fmaxf(a + b1[r], 0.f);
    __syncthreads();
    if (t < 512) {
        float acc = b2[t];
        #pragma unroll
        for (int rr = 0; rr < 32; rr++) acc += sh[rr] * w2[t * 32 + rr];
        g_s[t] = 1.f / (1.f + expf(-acc));
    }
}

// ---------------- 4. scale + transpose to pixel-major, plus sigmoid ----------------
__global__ void k_trans(const float* __restrict__ x) {
    __shared__ float tile[32][33];
    int p0 = blockIdx.x * 32, c0 = blockIdx.y * 32;
    int tx = threadIdx.x, ty = threadIdx.y;
    #pragma unroll
    for (int j = 0; j < 4; j++) {
        int ch = c0 + ty + j * 8;
        tile[ty + j * 8][tx] = x[ch * 1024 + p0 + tx] * g_s[ch];
    }
    __syncthreads();
    #pragma unroll
    for (int j = 0; j < 4; j++) {
        int p = p0 + ty + j * 8;
        float v = tile[tx][ty + j * 8];
        g_f0t[p * 512 + c0 + tx] = v;
        g_sigt[p * 512 + c0 + tx] = 1.f / (1.f + expf(-v));
    }
}

// ---------------- 5. separable gaussian pooling: B_c = A F_c A^T ----------------
__global__ void k_gauss(const float* __restrict__ x) {
    __shared__ float F[1024], T[1024], sA[1024], sAt[1024];
    int c = blockIdx.x, t = threadIdx.x;
    float s = g_s[c];
    for (int i = t; i < 1024; i += 256) {
        F[i] = x[c * 1024 + i] * s;
        float a = g_A[i];
        sA[i] = a;                                // sA[k*32+y]  = A[k][y]
        sAt[(i & 31) * 32 + (i >> 5)] = a;        // sAt[y*32+k] = A[k][y]
    }
    __syncthreads();
    // T[x][k] = sum_y A[k][y] * F[x][y]
    for (int idx = t; idx < 1024; idx += 256) {
        int xx = idx >> 5, k = idx & 31;
        float acc = 0.f;
        #pragma unroll
        for (int y = 0; y < 32; y++) acc += sAt[y * 32 + k] * F[xx * 32 + y];
        T[idx] = acc;
    }
    __syncthreads();
    // B[i][k] = sum_x A[i][x] * T[x][k] ; pix = i*32+k ; store pixel-major flat
    for (int idx = t; idx < 1024; idx += 256) {
        int i = idx >> 5, k = idx & 31;
        float acc = 0.f;
        #pragma unroll
        for (int xx = 0; xx < 32; xx++) acc += sA[i * 32 + xx] * T[xx * 32 + k];
        g_cat[idx * 512 + c] = acc;
    }
}

// ---------------- 6. 3x3 patch-correlation attention (block per pixel) ----------------
__global__ void k_csa() {
    int pix = blockIdx.x, pi = pix >> 5, pj = pix & 31;
    int t = threadIdx.x;
    int c0 = t, c1 = t + 256;
    __shared__ float wsum[8][9];
    __shared__ float sa[9];
    float acc[9];
    int np[9];
    bool ok[9];
    float sc0 = g_sigt[pix * 512 + c0];
    float sc1 = g_sigt[pix * 512 + c1];
    #pragma unroll
    for (int uv = 0; uv < 9; uv++) {
        int u = uv / 3, v = uv % 3;
        int ni = pi + u - 1, nj = pj + v - 1;
        ok[uv] = (ni >= 0 && ni < 32 && nj >= 0 && nj < 32);
        np[uv] = ni * 32 + nj;
        acc[uv] = 0.f;
        if (ok[uv])
            acc[uv] = sc0 * g_sigt[np[uv] * 512 + c0] + sc1 * g_sigt[np[uv] * 512 + c1];
    }
    #pragma unroll
    for (int uv = 0; uv < 9; uv++)
        #pragma unroll
        for (int o = 16; o; o >>= 1) acc[uv] += __shfl_down_sync(0xffffffffu, acc[uv], o);
    if ((t & 31) == 0) {
        #pragma unroll
        for (int uv = 0; uv < 9; uv++) wsum[t >> 5][uv] = acc[uv];
    }
    __syncthreads();
    if (t == 0) {
        float av[9], m = -1e30f;
        #pragma unroll
        for (int uv = 0; uv < 9; uv++) {
            float s2 = 0.f;
            #pragma unroll
            for (int w = 0; w < 8; w++) s2 += wsum[w][uv];
            av[uv] = s2 * (1.f / 512.f);
            m = fmaxf(m, av[uv]);
        }
        float se = 0.f;
        #pragma unroll
        for (int uv = 0; uv < 9; uv++) { av[uv] = expf(av[uv] - m); se += av[uv]; }
        float inv = 1.f / se;
        #pragma unroll
        for (int uv = 0; uv < 9; uv++) sa[uv] = av[uv] * inv;
    }
    __syncthreads();
    float o0 = 0.f, o1 = 0.f;
    #pragma unroll
    for (int uv = 0; uv < 9; uv++) {
        if (ok[uv]) {
            float a = sa[uv];
            o0 += a * g_f0t[np[uv] * 512 + c0];
            o1 += a * g_f0t[np[uv] * 512 + c1];
        }
    }
    g_cat[524288 + pix * 512 + c0] = o0;
    g_cat[524288 + pix * 512 + c1] = o1;
}

// ---------------- 7. down GEMM: z[512,1024] = W[512,1024] @ cat[1024,1024] ----------------
__global__ void k_gemm(const float* __restrict__ Wd, float* __restrict__ out) {
    __shared__ float As[16][64];   // As[k][m]
    __shared__ float Bs[16][64];   // Bs[k][n]
    int t = threadIdx.x;
    int tx = t & 15, ty = t >> 4;
    int m0 = blockIdx.y * 64, n0 = blockIdx.x * 64;
    int lr = t >> 2, lc = (t & 3) * 4;      // W tile: row lr (0..63), k-offset lc
    int br = t >> 4, bc = (t & 15) * 4;     // cat tile: row br (0..15), n-offset bc
    const float* wp = Wd + (m0 + lr) * 1024 + lc;
    const float* bp = g_cat + br * 1024 + n0 + bc;
    float acc[4][4] = {};
    for (int k0 = 0; k0 < 1024; k0 += 16) {
        float4 wa = *(const float4*)(wp + k0);
        float4 cb = *(const float4*)(bp + k0 * 1024);
        __syncthreads();
        As[lc + 0][lr] = wa.x;
        As[lc + 1][lr] = wa.y;
        As[lc + 2][lr] = wa.z;
        As[lc + 3][lr] = wa.w;
        *(float4*)&Bs[br][bc] = cb;
        __syncthreads();
        #pragma unroll
        for (int k = 0; k < 16; k++) {
            float4 a = *(float4*)&As[k][ty * 4];
            float4 b = *(float4*)&Bs[k][tx * 4];
            acc[0][0] += a.x * b.x; acc[0][1] += a.x * b.y; acc[0][2] += a.x * b.z; acc[0][3] += a.x * b.w;
            acc[1][0] += a.y * b.x; acc[1][1] += a.y * b.y; acc[1][2] += a.y * b.z; acc[1][3] += a.y * b.w;
            acc[2][0] += a.z * b.x; acc[2][1] += a.z * b.y; acc[2][2] += a.z * b.z; acc[2][3] += a.z * b.w;
            acc[3][0] += a.w * b.x; acc[3][1] += a.w * b.y; acc[3][2] += a.w * b.z; acc[3][3] += a.w * b.w;
        }
    }
    #pragma unroll
    for (int i = 0; i < 4; i++) {
        float4 r = make_float4(acc[i][0], acc[i][1], acc[i][2], acc[i][3]);
        *(float4*)(out + (m0 + ty * 4 + i) * 1024 + n0 + tx * 4) = r;
    }
}

// ---------------- 8. instance norm + leaky relu (in place) ----------------
__global__ void k_norm(float* __restrict__ out) {
    int o = blockIdx.x, t = threadIdx.x;
    float4* row = (float4*)(out + o * 1024);
    float4 v = row[t];
    float s = v.x + v.y + v.z + v.w;
    float ss = v.x * v.x + v.y * v.y + v.z * v.z + v.w * v.w;
    #pragma unroll
    for (int off = 16; off; off >>= 1) {
        s  += __shfl_down_sync(0xffffffffu, s, off);
        ss += __shfl_down_sync(0xffffffffu, ss, off);
    }
    __shared__ float w1s[8], w2s[8];
    __shared__ float smean, sinv;
    if ((t & 31) == 0) { w1s[t >> 5] = s; w2s[t >> 5] = ss; }
    __syncthreads();
    if (t == 0) {
        float ts = 0.f, tss = 0.f;
        #pragma unroll
        for (int i = 0; i < 8; i++) { ts += w1s[i]; tss += w2s[i]; }
        float mu = ts * (1.f / 1024.f);
        float var = tss * (1.f / 1024.f) - mu * mu;
        smean = mu;
        sinv = 1.f / sqrtf(var + 1e-5f);
    }
    __syncthreads();
    float mu = smean, inv = sinv;
    float a;
    a = (v.x - mu) * inv; v.x = a >= 0.f ? a : 0.2f * a;
    a = (v.y - mu) * inv; v.y = a >= 0.f ? a : 0.2f * a;
    a = (v.z - mu) * inv; v.z = a >= 0.f ? a : 0.2f * a;
    a = (v.w - mu) * inv; v.w = a >= 0.f ? a : 0.2f * a;
    row[t] = v;
}

// ---------------- launch ----------------
extern "C" void kernel_launch(void* const* d_in, const int* in_sizes, int n_in,
                              void* d_out, int out_size) {
    const float* x  = (const float*)d_in[0];   // (1,512,32,32)
    const float* w1 = (const float*)d_in[1];   // (32,512)
    const float* b1 = (const float*)d_in[2];   // (32)
    const float* w2 = (const float*)d_in[3];   // (512,32)
    const float* b2 = (const float*)d_in[4];   // (512)
    const float* dw = (const float*)d_in[5];   // (512,1024)
    float* out = (float*)d_out;                // (1,512,32,32) fp32

    k_initA<<<1, 1024>>>();
    k_mean<<<512, 256>>>(x);
    k_mlp<<<1, 1024>>>(w1, b1, w2, b2);
    k_trans<<<dim3(32, 16), dim3(32, 8)>>>(x);
    k_gauss<<<512, 256>>>(x);
    k_csa<<<1024, 256>>>();
    k_gemm<<<dim3(16, 8), 256>>>(dw, out);
    k_norm<<<512, 256>>>(out);
}